// round 2
// baseline (speedup 1.0000x reference)
#include <cuda_runtime.h>

#define D   256
#define H   4
#define DK  64
#define NV_CAP 65536
#define NE_CAP (1 << 19)   // >= 320000, so compaction can never overflow
#define B_CAP  128

// ---------------- scratch (static __device__ — no allocations) ----------------
__device__ int      d_inv[NV_CAP];          // node -> query row, -1 otherwise
__device__ int      d_count;                // number of relevant edges
__device__ float    d_qg[B_CAP * D];        // query @ WQ^T
__device__ float    d_qW[B_CAP * H * D];    // per-head (q folded with WK) * scale
__device__ int      d_esrc[NE_CAP];         // compacted edge src
__device__ int      d_eb[NE_CAP];           // compacted edge dst-as-query-row
__device__ float    d_es[NE_CAP * H];       // scores, then exp(s-m) in-place
__device__ unsigned d_mkey[B_CAP * H];      // monotone-uint key of running max
__device__ float    d_denom[B_CAP * H];     // softmax denominators
__device__ float    d_aggx[B_CAP * H * D];  // sum_e alpha_e * x[src]
__device__ float    d_mid[B_CAP * D];       // WV applied to aggx

// monotone order-preserving float<->uint key (works for negatives)
__device__ __forceinline__ unsigned fkey(float f) {
    unsigned u = __float_as_uint(f);
    return (u & 0x80000000u) ? ~u : (u | 0x80000000u);
}
__device__ __forceinline__ float funkey(unsigned u) {
    return __uint_as_float((u & 0x80000000u) ? (u ^ 0x80000000u) : ~u);
}

// ---------------- K0: init all per-launch state ----------------
__global__ void k_init(int nv) {
    int i = blockIdx.x * blockDim.x + threadIdx.x;
    int stride = gridDim.x * blockDim.x;
    for (int idx = i; idx < nv; idx += stride) d_inv[idx] = -1;
    if (i < B_CAP * H * D) d_aggx[i] = 0.0f;
    if (i < B_CAP * H) { d_denom[i] = 0.0f; d_mkey[i] = 0u; }
    if (i == 0) d_count = 0;
}

// ---------------- K1: scatter glob_idx -> inverse map (int32 indices!) ----------------
__global__ void k_scatter(const int* __restrict__ glob, int bn) {
    int t = blockIdx.x * blockDim.x + threadIdx.x;
    if (t < bn) {
        unsigned g = (unsigned)glob[t];
        if (g < NV_CAP) d_inv[g] = t;
    }
}

// ---------------- K2: qg = query @ WQ^T  (block=b, thread=c) ----------------
__global__ void k_qg(const float* __restrict__ query, const float* __restrict__ WQ) {
    __shared__ float qrow[D];
    int b = blockIdx.x, c = threadIdx.x;
    qrow[c] = query[b * D + c];
    __syncthreads();
    float acc = 0.0f;
    const float* w = WQ + c * D;
#pragma unroll 8
    for (int d = 0; d < D; d++) acc += qrow[d] * w[d];
    d_qg[b * D + c] = acc;
}

// ---------------- K3: qW[b,h,d] = sum_j qg[b,h*64+j]*WK[h*64+j,d] * 1/sqrt(dk) ----------------
__global__ void k_qw(const float* __restrict__ WK) {
    __shared__ float q[D];
    int b = blockIdx.x, d = threadIdx.x;
    q[d] = d_qg[b * D + d];
    __syncthreads();
    for (int h = 0; h < H; h++) {
        float acc = 0.0f;
#pragma unroll 8
        for (int j = 0; j < DK; j++)
            acc += q[h * DK + j] * WK[(h * DK + j) * D + d];
        d_qW[(b * H + h) * D + d] = acc * 0.125f;  // 1/sqrt(64) folded in
    }
}

// ---------------- K4a: scan all edges, compact those with dst in glob set ----------------
__global__ void k_scan(const int* __restrict__ dst,
                       const int* __restrict__ src, int ne) {
    int e = blockIdx.x * blockDim.x + threadIdx.x;
    if (e >= ne) return;
    unsigned dv = (unsigned)dst[e];
    if (dv >= NV_CAP) return;          // safety: never fault
    int b = d_inv[dv];
    if (b < 0) return;
    int pos = atomicAdd(&d_count, 1);
    if (pos < NE_CAP) { d_esrc[pos] = src[e]; d_eb[pos] = b; }
}

// ---------------- K4b: per-edge scores s[h] = x[src] . qW[b,h] ----------------
// block = 256 threads (8 warps). Shuffle reduction per head, smem combine.
__global__ void k_score(const float* __restrict__ x) {
    __shared__ float red[8];
    int n = min(d_count, NE_CAP);
    int d = threadIdx.x;
    int lane = d & 31, warp = d >> 5;
    for (int i = blockIdx.x; i < n; i += gridDim.x) {
        int s = d_esrc[i], b = d_eb[i];
        float xv = x[(long)s * D + d];
        const float* qb = d_qW + b * H * D;
#pragma unroll
        for (int h = 0; h < H; h++) {
            float v = xv * qb[h * D + d];
#pragma unroll
            for (int off = 16; off > 0; off >>= 1)
                v += __shfl_xor_sync(0xffffffffu, v, off);
            if (lane == 0) red[warp] = v;
            __syncthreads();
            if (d == 0) {
                float sc = red[0] + red[1] + red[2] + red[3]
                         + red[4] + red[5] + red[6] + red[7];
                d_es[i * H + h] = sc;
                atomicMax(&d_mkey[b * H + h], fkey(sc));
            }
            __syncthreads();
        }
    }
}

// ---------------- K5: e = exp(s - m); denom += e ----------------
__global__ void k_exp() {
    int n = min(d_count, NE_CAP);
    int stride = gridDim.x * blockDim.x;
    for (int i = blockIdx.x * blockDim.x + threadIdx.x; i < n; i += stride) {
        int b = d_eb[i];
#pragma unroll
        for (int h = 0; h < H; h++) {
            float m = funkey(d_mkey[b * H + h]);
            float e = expf(d_es[i * H + h] - m);
            d_es[i * H + h] = e;
            atomicAdd(&d_denom[b * H + h], e);
        }
    }
}

// ---------------- K5b: aggx[b,h,:] += (e/denom) * x[src,:] ----------------
__global__ void k_agg(const float* __restrict__ x) {
    __shared__ float w[H];
    int n = min(d_count, NE_CAP);
    int t = threadIdx.x;
    for (int i = blockIdx.x; i < n; i += gridDim.x) {
        int s = d_esrc[i], b = d_eb[i];
        if (t < H) w[t] = d_es[i * H + t] / d_denom[b * H + t];
        __syncthreads();
        float xv = x[(long)s * D + t];
#pragma unroll
        for (int h = 0; h < H; h++)
            atomicAdd(&d_aggx[(b * H + h) * D + t], w[h] * xv);
        __syncthreads();
    }
}

// ---------------- K6: mid[b, h*64+j] = sum_d WV[h*64+j, d] * aggx[b,h,d] ----------------
__global__ void k_wv(const float* __restrict__ WV) {
    __shared__ float ax[H * D];
    int b = blockIdx.x, t = threadIdx.x;
    for (int k = t; k < H * D; k += blockDim.x) ax[k] = d_aggx[b * H * D + k];
    __syncthreads();
    int h = t / DK;
    float acc = 0.0f;
#pragma unroll 8
    for (int d = 0; d < D; d++) acc += WV[t * D + d] * ax[h * D + d];
    d_mid[b * D + t] = acc;
}

// ---------------- K7: r[b,o] = sum_c mid[b,c] * WO[o,c] ----------------
__global__ void k_wo(const float* __restrict__ WO, float* __restrict__ out) {
    __shared__ float mid[D];
    int b = blockIdx.x, o = threadIdx.x;
    mid[o] = d_mid[b * D + o];
    __syncthreads();
    float acc = 0.0f;
#pragma unroll 8
    for (int c = 0; c < D; c++) acc += WO[o * D + c] * mid[c];
    out[b * D + o] = acc;
}

extern "C" void kernel_launch(void* const* d_in, const int* in_sizes, int n_in,
                              void* d_out, int out_size) {
    const float* query = (const float*)d_in[0];
    const float* x     = (const float*)d_in[1];
    const float* WQ    = (const float*)d_in[2];
    const float* WK    = (const float*)d_in[3];
    const float* WV    = (const float*)d_in[4];
    const float* WO    = (const float*)d_in[5];
    const int*   src   = (const int*)d_in[6];   // JAX x64 disabled: int64 -> int32
    const int*   dst   = (const int*)d_in[7];
    const int*   glob  = (const int*)d_in[8];

    int bn = in_sizes[8];        // 64
    int nv = in_sizes[1] / D;    // 40000
    int ne = in_sizes[6];        // 320000

    k_init<<<512, 256>>>(nv);
    k_scatter<<<(bn + 63) / 64, 64>>>(glob, bn);
    k_qg<<<bn, 256>>>(query, WQ);
    k_qw<<<bn, 256>>>(WK);
    k_scan<<<(ne + 255) / 256, 256>>>(dst, src, ne);
    k_score<<<512, 256>>>(x);
    k_exp<<<32, 256>>>();
    k_agg<<<512, 256>>>(x);
    k_wv<<<bn, 256>>>(WV);
    k_wo<<<bn, 256>>>(WO, (float*)d_out);
}

// round 3
// speedup vs baseline: 1.4961x; 1.4961x over previous
#include <cuda_runtime.h>

#define D    256
#define H    4
#define DK   64
#define B_CAP 128
#define BCAP 8192   // per-b edge bucket capacity (expected ~8, Poisson; huge headroom)

// ---------------- scratch (static __device__ — no allocations) ----------------
__device__ float d_qW[B_CAP * H * D];     // per-head (q @ WQ^T folded with WK) * 1/sqrt(dk)
__device__ int   d_bcnt[B_CAP];           // per-b relevant-edge count
__device__ int   d_bsrc[B_CAP * BCAP];    // per-b src node lists

// ============ K1: qW[b,h,:] = (query[b] @ WQ^T)[h-block] @ WK[h-block] * 0.125 ============
// grid (bn, H), block 256. Also zeroes the bucket counters (runs before k_scan in stream).
__global__ void k_qw(const float* __restrict__ query,
                     const float* __restrict__ WQ,
                     const float* __restrict__ WK) {
    __shared__ float qs[D];     // query row
    __shared__ float qgh[DK];   // qg slice for this head
    int b = blockIdx.x, h = blockIdx.y, t = threadIdx.x;
    int lane = t & 31, warp = t >> 5;
    if (h == 0 && t == 0) d_bcnt[b] = 0;
    qs[t] = query[b * D + t];
    __syncthreads();
    // qgh[j] = sum_c qs[c] * WQ[(h*64+j)*D + c], 8 warps x 8 j's
#pragma unroll
    for (int jj = 0; jj < 8; jj++) {
        int j = warp * 8 + jj;
        const float* wq = WQ + (h * DK + j) * D;
        float v = 0.f;
#pragma unroll
        for (int k2 = 0; k2 < 8; k2++) { int c = lane + 32 * k2; v += qs[c] * wq[c]; }
#pragma unroll
        for (int off = 16; off > 0; off >>= 1) v += __shfl_xor_sync(0xffffffffu, v, off);
        if (lane == 0) qgh[j] = v;
    }
    __syncthreads();
    // qW[d] = sum_j qgh[j] * WK[(h*64+j)*D + d] * 1/sqrt(64)
    float acc = 0.f;
#pragma unroll 8
    for (int j = 0; j < DK; j++) acc += qgh[j] * WK[(h * DK + j) * D + t];
    d_qW[(b * H + h) * D + t] = acc * 0.125f;
}

// ============ K2: scan edges, bucket those whose dst is a global node ============
// Per-block smem hash of glob ids (256 slots), int4 dst loads, src loaded only on hit.
__global__ void k_scan(const int* __restrict__ dst, const int* __restrict__ src,
                       const int* __restrict__ glob, int bn, int ne) {
    __shared__ int hk[256];
    __shared__ int hv[256];
    int t = threadIdx.x;
    hk[t] = -1;
    __syncthreads();
    if (t < bn) {
        int g = glob[t];
        unsigned slot = ((unsigned)g * 2654435761u) >> 24;
        for (;;) {
            int prev = atomicCAS(&hk[slot & 255], -1, g);
            if (prev == -1) { hv[slot & 255] = t; break; }
            if (prev == g) break;   // duplicate glob id: first insert wins
            slot++;
        }
    }
    __syncthreads();

    int gid = blockIdx.x * blockDim.x + t;
    int base = gid * 4;
    int lim = min(base + 4, ne);
    if (base >= ne) return;
    if (base + 4 <= ne) {
        int4 dv = *(const int4*)(dst + base);
        int ds[4] = {dv.x, dv.y, dv.z, dv.w};
#pragma unroll
        for (int k = 0; k < 4; k++) {
            int g = ds[k];
            unsigned slot = ((unsigned)g * 2654435761u) >> 24;
            int bf = -1;
            for (;;) {
                int kk = hk[slot & 255];
                if (kk == -1) break;
                if (kk == g) { bf = hv[slot & 255]; break; }
                slot++;
            }
            if (bf >= 0) {
                int pos = atomicAdd(&d_bcnt[bf], 1);
                if (pos < BCAP) d_bsrc[bf * BCAP + pos] = src[base + k];
            }
        }
    } else {
        for (int e = base; e < lim; e++) {
            int g = dst[e];
            unsigned slot = ((unsigned)g * 2654435761u) >> 24;
            int bf = -1;
            for (;;) {
                int kk = hk[slot & 255];
                if (kk == -1) break;
                if (kk == g) { bf = hv[slot & 255]; break; }
                slot++;
            }
            if (bf >= 0) {
                int pos = atomicAdd(&d_bcnt[bf], 1);
                if (pos < BCAP) d_bsrc[bf * BCAP + pos] = src[e];
            }
        }
    }
}

// ============ K3: per-b online-softmax attention + WV + WO, all in one block ============
// grid bn, block 256.
__global__ void k_mega(const float* __restrict__ x,
                       const float* __restrict__ WV,
                       const float* __restrict__ WO,
                       float* __restrict__ out) {
    __shared__ float qWs[H * D];    // 4 KB
    __shared__ float aggx[H * D];   // 4 KB
    __shared__ float red[8 * H];
    __shared__ float fw[2 * H];     // [0..H): rescale f, [H..2H): weight w
    __shared__ float mh[H], dh[H];
    __shared__ float mid[D];
    int b = blockIdx.x, t = threadIdx.x;
    int lane = t & 31, warp = t >> 5;

#pragma unroll
    for (int h = 0; h < H; h++) {
        qWs[h * D + t] = d_qW[(b * H + h) * D + t];
        aggx[h * D + t] = 0.f;
    }
    if (t < H) { mh[t] = -3.4e38f; dh[t] = 0.f; }
    __syncthreads();

    int n = min(d_bcnt[b], BCAP);
    for (int i = 0; i < n; i++) {
        int s = d_bsrc[b * BCAP + i];
        float xv = x[(size_t)s * D + t];
        float p[H];
#pragma unroll
        for (int h = 0; h < H; h++) {
            float v = xv * qWs[h * D + t];
#pragma unroll
            for (int off = 16; off > 0; off >>= 1) v += __shfl_xor_sync(0xffffffffu, v, off);
            p[h] = v;
        }
        if (lane == 0) {
#pragma unroll
            for (int h = 0; h < H; h++) red[warp * H + h] = p[h];
        }
        __syncthreads();
        if (t < H) {
            float sc = 0.f;
#pragma unroll
            for (int w2 = 0; w2 < 8; w2++) sc += red[w2 * H + t];
            float mo = mh[t], mn = fmaxf(mo, sc);
            float f = __expf(mo - mn);   // first edge: exp(-big) -> 0
            float w = __expf(sc - mn);
            dh[t] = dh[t] * f + w;
            mh[t] = mn;
            fw[t] = f; fw[H + t] = w;
        }
        __syncthreads();
#pragma unroll
        for (int h = 0; h < H; h++)
            aggx[h * D + t] = aggx[h * D + t] * fw[h] + fw[H + h] * xv;
        __syncthreads();
    }

    // normalize (nodes with no edges -> exact 0, matching reference)
#pragma unroll
    for (int h = 0; h < H; h++) {
        float dn = dh[h];
        aggx[h * D + t] = dn > 0.f ? aggx[h * D + t] / dn : 0.f;
    }
    __syncthreads();

    // mid[t] = sum_d WV[t,d] * aggx[t/64, d]
    {
        int h = t >> 6;
        const float* wr = WV + t * D;
        float acc = 0.f;
#pragma unroll 8
        for (int d2 = 0; d2 < D; d2++) acc += wr[d2] * aggx[h * D + d2];
        mid[t] = acc;
    }
    __syncthreads();

    // out[b,t] = sum_c WO[t,c] * mid[c]
    {
        const float* wr = WO + t * D;
        float acc = 0.f;
#pragma unroll 8
        for (int c = 0; c < D; c++) acc += wr[c] * mid[c];
        out[b * D + t] = acc;
    }
}

extern "C" void kernel_launch(void* const* d_in, const int* in_sizes, int n_in,
                              void* d_out, int out_size) {
    const float* query = (const float*)d_in[0];
    const float* x     = (const float*)d_in[1];
    const float* WQ    = (const float*)d_in[2];
    const float* WK    = (const float*)d_in[3];
    const float* WV    = (const float*)d_in[4];
    const float* WO    = (const float*)d_in[5];
    const int*   src   = (const int*)d_in[6];   // JAX x64 disabled: stored as int32
    const int*   dst   = (const int*)d_in[7];
    const int*   glob  = (const int*)d_in[8];

    int bn = in_sizes[8];              // 64
    if (bn > B_CAP) bn = B_CAP;
    int ne = in_sizes[6];              // 320000

    dim3 g1(bn, H);
    k_qw<<<g1, 256>>>(query, WQ, WK);                       // also zeroes d_bcnt
    int nthr = (ne + 3) / 4;
    k_scan<<<(nthr + 255) / 256, 256>>>(dst, src, glob, bn, ne);
    k_mega<<<bn, 256>>>(x, WV, WO, (float*)d_out);
}

// round 4
// speedup vs baseline: 4.9596x; 3.3150x over previous
#include <cuda_runtime.h>

#define D     256
#define H     4
#define DK    64
#define B_CAP 128
#define BCAP  8192   // per-b bucket capacity in global
#define SC_CAP 512   // per-b edges processed (Poisson mean ~8; 512 = absurd headroom)

// ---------------- scratch (static __device__ — no allocations) ----------------
__device__ float d_qW[B_CAP * H * D];     // folded (q @ WQ^T) @ WK * 1/sqrt(dk)
__device__ int   d_bcnt[B_CAP];
__device__ int   d_bsrc[B_CAP * BCAP];

// ============ K1: qW[b,h,:] — grid (bn,H), block 256. Zeroes bucket counters. ============
__global__ void k_qw(const float* __restrict__ query,
                     const float* __restrict__ WQ,
                     const float* __restrict__ WK) {
    __shared__ float4 qs4[64];    // query row as float4
    __shared__ float  qgh[DK];    // qg slice for this head
    int b = blockIdx.x, h = blockIdx.y, t = threadIdx.x;
    int lane = t & 31, warp = t >> 5;
    if (h == 0 && t == 0) d_bcnt[b] = 0;
    if (t < 64) qs4[t] = ((const float4*)query)[b * 64 + t];
    __syncthreads();

    // phase 1: qgh[j] = q . WQ[h*64+j], 8 warps x 8 rows, 4-row ILP batches
    float4 qa = qs4[lane], qb = qs4[lane + 32];
#pragma unroll
    for (int g = 0; g < 2; g++) {
        float v[4];
#pragma unroll
        for (int r = 0; r < 4; r++) {
            int j = warp * 8 + g * 4 + r;
            const float4* wq = (const float4*)WQ + (size_t)(h * DK + j) * 64;
            float4 a = wq[lane], c = wq[lane + 32];
            v[r] = a.x * qa.x + a.y * qa.y + a.z * qa.z + a.w * qa.w
                 + c.x * qb.x + c.y * qb.y + c.z * qb.z + c.w * qb.w;
        }
#pragma unroll
        for (int off = 16; off > 0; off >>= 1) {
#pragma unroll
            for (int r = 0; r < 4; r++) v[r] += __shfl_xor_sync(0xffffffffu, v[r], off);
        }
        if (lane < 4) qgh[warp * 8 + g * 4 + lane] = v[lane];
    }
    __syncthreads();

    // phase 2: qW[d] = sum_j qgh[j] * WK[(h*64+j), d] * 0.125
    float acc = 0.f;
#pragma unroll 16
    for (int j = 0; j < DK; j++) acc += qgh[j] * WK[(size_t)(h * DK + j) * D + t];
    d_qW[(b * H + h) * D + t] = acc * 0.125f;
}

// ============ K2: scan edges, bucket hits via smem hash of glob ids ============
__global__ void k_scan(const int* __restrict__ dst, const int* __restrict__ src,
                       const int* __restrict__ glob, int bn, int ne) {
    __shared__ int hk[256];
    __shared__ int hv[256];
    int t = threadIdx.x;
    hk[t] = -1;
    __syncthreads();
    if (t < bn) {
        int g = glob[t];
        unsigned slot = ((unsigned)g * 2654435761u) >> 24;
        for (;;) {
            int prev = atomicCAS(&hk[slot & 255], -1, g);
            if (prev == -1) { hv[slot & 255] = t; break; }
            if (prev == g) break;
            slot++;
        }
    }
    __syncthreads();

    int gid = blockIdx.x * blockDim.x + t;
    int base = gid * 4;
    if (base >= ne) return;
    int ds[4];
    if (base + 4 <= ne) {
        int4 dv = *(const int4*)(dst + base);
        ds[0] = dv.x; ds[1] = dv.y; ds[2] = dv.z; ds[3] = dv.w;
    } else {
        for (int k = 0; k < 4; k++) ds[k] = (base + k < ne) ? dst[base + k] : -1;
    }
#pragma unroll
    for (int k = 0; k < 4; k++) {
        int g = ds[k];
        if (g < 0) continue;
        unsigned slot = ((unsigned)g * 2654435761u) >> 24;
        int bf = -1;
        for (;;) {
            int kk = hk[slot & 255];
            if (kk == -1) break;
            if (kk == g) { bf = hv[slot & 255]; break; }
            slot++;
        }
        if (bf >= 0) {
            int pos = atomicAdd(&d_bcnt[bf], 1);
            if (pos < BCAP) d_bsrc[bf * BCAP + pos] = src[base + k];
        }
    }
}

// ============ K3: per-b attention, fully phase-parallel. grid bn, block 256. ============
__global__ void k_mega(const float* __restrict__ x,
                       const float* __restrict__ WV,
                       const float* __restrict__ WO,
                       float* __restrict__ out) {
    __shared__ float4 qW4[H * 64];       // 4 KB
    __shared__ int    slist[SC_CAP];     // 2 KB
    __shared__ float  sc[SC_CAP * H];    // 8 KB: scores, then alpha in place
    __shared__ float  ax[H * D];         // 4 KB
    __shared__ float  mid[D];            // 1 KB
    int b = blockIdx.x, t = threadIdx.x;
    int lane = t & 31, warp = t >> 5;
    const float4* x4 = (const float4*)x;

    qW4[t] = ((const float4*)d_qW)[b * 256 + t];
    int n = d_bcnt[b];
    if (n > SC_CAP) n = SC_CAP;
    for (int i = t; i < n; i += 256) slist[i] = d_bsrc[b * BCAP + i];
    __syncthreads();

    // -------- Phase A: warp-per-edge scores, 4 heads interleaved --------
    for (int base = 0; base < n; base += 8) {
        int i = base + warp;
        if (i < n) {
            int s = slist[i];
            float4 xa = x4[(size_t)s * 64 + lane];
            float4 xb = x4[(size_t)s * 64 + 32 + lane];
            float v[H];
#pragma unroll
            for (int h = 0; h < H; h++) {
                float4 qa = qW4[h * 64 + lane], qb = qW4[h * 64 + 32 + lane];
                v[h] = xa.x * qa.x + xa.y * qa.y + xa.z * qa.z + xa.w * qa.w
                     + xb.x * qb.x + xb.y * qb.y + xb.z * qb.z + xb.w * qb.w;
            }
#pragma unroll
            for (int off = 16; off > 0; off >>= 1) {
#pragma unroll
                for (int h = 0; h < H; h++) v[h] += __shfl_xor_sync(0xffffffffu, v[h], off);
            }
            if (lane < H) sc[i * H + lane] = v[lane];
        }
    }
    __syncthreads();

    // -------- Phase B: warp-per-head softmax (lane-parallel over edges) --------
    if (warp < H) {
        int h = warp;
        float m = -3.4e38f;
        for (int i = lane; i < n; i += 32) m = fmaxf(m, sc[i * H + h]);
#pragma unroll
        for (int off = 16; off > 0; off >>= 1)
            m = fmaxf(m, __shfl_xor_sync(0xffffffffu, m, off));
        float sum = 0.f;
        for (int i = lane; i < n; i += 32) sum += __expf(sc[i * H + h] - m);
#pragma unroll
        for (int off = 16; off > 0; off >>= 1)
            sum += __shfl_xor_sync(0xffffffffu, sum, off);
        float inv = (sum > 0.f) ? 1.f / sum : 0.f;
        for (int i = lane; i < n; i += 32)
            sc[i * H + h] = __expf(sc[i * H + h] - m) * inv;
    }
    __syncthreads();

    // -------- Phase C: sync-free aggregation, thread t = dim d --------
    {
        float a0 = 0.f, a1 = 0.f, a2 = 0.f, a3 = 0.f;
#pragma unroll 4
        for (int i = 0; i < n; i++) {
            float xv = x[(size_t)slist[i] * D + t];
            a0 += sc[i * H + 0] * xv;
            a1 += sc[i * H + 1] * xv;
            a2 += sc[i * H + 2] * xv;
            a3 += sc[i * H + 3] * xv;
        }
        ax[0 * D + t] = a0; ax[1 * D + t] = a1;
        ax[2 * D + t] = a2; ax[3 * D + t] = a3;
    }
    __syncthreads();

    // -------- Phase D1: mid[r] = WV[r,:] . ax[head(r),:], warp-per-row float4 --------
    const float4* WV4 = (const float4*)WV;
#pragma unroll
    for (int g = 0; g < 16; g++) {
        float v[2];
#pragma unroll
        for (int r2 = 0; r2 < 2; r2++) {
            int r = warp * 32 + g * 2 + r2;
            int hb = (r >> 6) * D;
            float4 a = WV4[(size_t)r * 64 + lane];
            float4 c = WV4[(size_t)r * 64 + 32 + lane];
            int d0 = 4 * lane, d1 = 128 + 4 * lane;
            v[r2] = a.x * ax[hb + d0] + a.y * ax[hb + d0 + 1]
                  + a.z * ax[hb + d0 + 2] + a.w * ax[hb + d0 + 3]
                  + c.x * ax[hb + d1] + c.y * ax[hb + d1 + 1]
                  + c.z * ax[hb + d1 + 2] + c.w * ax[hb + d1 + 3];
        }
#pragma unroll
        for (int off = 16; off > 0; off >>= 1) {
            v[0] += __shfl_xor_sync(0xffffffffu, v[0], off);
            v[1] += __shfl_xor_sync(0xffffffffu, v[1], off);
        }
        if (lane < 2) mid[warp * 32 + g * 2 + lane] = v[lane];
    }
    __syncthreads();

    // -------- Phase D2: out[b,r] = WO[r,:] . mid --------
    const float4* WO4 = (const float4*)WO;
#pragma unroll
    for (int g = 0; g < 16; g++) {
        float v[2];
#pragma unroll
        for (int r2 = 0; r2 < 2; r2++) {
            int r = warp * 32 + g * 2 + r2;
            float4 a = WO4[(size_t)r * 64 + lane];
            float4 c = WO4[(size_t)r * 64 + 32 + lane];
            int d0 = 4 * lane, d1 = 128 + 4 * lane;
            v[r2] = a.x * mid[d0] + a.y * mid[d0 + 1]
                  + a.z * mid[d0 + 2] + a.w * mid[d0 + 3]
                  + c.x * mid[d1] + c.y * mid[d1 + 1]
                  + c.z * mid[d1 + 2] + c.w * mid[d1 + 3];
        }
#pragma unroll
        for (int off = 16; off > 0; off >>= 1) {
            v[0] += __shfl_xor_sync(0xffffffffu, v[0], off);
            v[1] += __shfl_xor_sync(0xffffffffu, v[1], off);
        }
        if (lane < 2) out[b * D + warp * 32 + g * 2 + lane] = v[lane];
    }
}

extern "C" void kernel_launch(void* const* d_in, const int* in_sizes, int n_in,
                              void* d_out, int out_size) {
    const float* query = (const float*)d_in[0];
    const float* x     = (const float*)d_in[1];
    const float* WQ    = (const float*)d_in[2];
    const float* WK    = (const float*)d_in[3];
    const float* WV    = (const float*)d_in[4];
    const float* WO    = (const float*)d_in[5];
    const int*   src   = (const int*)d_in[6];   // JAX x64 disabled: stored as int32
    const int*   dst   = (const int*)d_in[7];
    const int*   glob  = (const int*)d_in[8];

    int bn = in_sizes[8];              // 64
    if (bn > B_CAP) bn = B_CAP;
    int ne = in_sizes[6];              // 320000

    dim3 g1(bn, H);
    k_qw<<<g1, 256>>>(query, WQ, WK);  // also zeroes d_bcnt
    int nthr = (ne + 3) / 4;
    k_scan<<<(nthr + 255) / 256, 256>>>(dst, src, glob, bn, ne);
    k_mega<<<bn, 256>>>(x, WV, WO, (float*)d_out);
}